// round 6
// baseline (speedup 1.0000x reference)
#include <cuda_runtime.h>

#define NN 4096
#define EE 16384
#define DD 13
#define RR 128
#define NP 4
#define HOSTRIDE 132
#define PBLK 8
#define EPB  (EE / PBLK)          // 2048 edges per prep block
#define PCAP (EPB / 2 + 64)       // max pairs per region (incl. per-key padding)

__device__ int g_pairs[PBLK * PCAP * 2];
__device__ int g_cnt[PBLK];

// k_main smem layout (floats)
#define S_BP   0
#define S_BPB  (NP * DD * RR)
#define S_HO   (S_BPB + NP * RR)
#define S_HOB  (S_HO + 3 * NP * DD * HOSTRIDE)
#define S_TOT  (S_HOB + 3 * NP * DD)   // 27916 floats ~ 109.1 KiB

// ---- prep: per-region bucket sort by type key, emit padded type-uniform pairs
__global__ void __launch_bounds__(1024, 1) k_prep(const int* __restrict__ et,
                                                  float* __restrict__ out) {
    __shared__ int hist[64], bstart[64], cursor[64], pb[64];
    __shared__ short sorted[EPB];
    __shared__ unsigned char keys[EPB], skey[EPB];
    const int tid = threadIdx.x;
    const int bi  = blockIdx.x;
    const int base = bi * EPB;

    // zero output slice (replaces a separate k_zero kernel)
    for (int i = tid; i < NN * DD / PBLK; i += 1024) out[bi * (NN * DD / PBLK) + i] = 0.f;
    // fill region with -1 (padding sentinel)
    for (int i = tid; i < PCAP * 2; i += 1024) g_pairs[bi * PCAP * 2 + i] = -1;

    if (tid < 64) hist[tid] = 0;
    __syncthreads();
    for (int i = tid; i < EPB; i += 1024) {
        int e = base + i;
        int k = __ldg(et + e * 3) * 16 + __ldg(et + e * 3 + 1) * 4 + __ldg(et + e * 3 + 2);
        keys[i] = (unsigned char)k;
        atomicAdd(&hist[k], 1);
    }
    __syncthreads();
    if (tid == 0) {
        int run = 0, rp = 0;
        for (int k = 0; k < 64; k++) {
            bstart[k] = run; cursor[k] = run; run += hist[k];
            pb[k] = rp; rp += (hist[k] + 1) >> 1;   // ceil pairs
        }
        g_cnt[bi] = rp;
    }
    __syncthreads();
    for (int i = tid; i < EPB; i += 1024) {
        int k = keys[i];
        int pos = atomicAdd(&cursor[k], 1);
        sorted[pos] = (short)i;
        skey[pos] = (unsigned char)k;
    }
    __syncthreads();
    for (int i = tid; i < EPB; i += 1024) {
        int k = skey[i];
        int r = i - bstart[k];
        g_pairs[bi * PCAP * 2 + pb[k] * 2 + r] = base + (int)sorted[i];
    }
}

// ---- warp reduction of 13 streams via redistribution tree -------------------
__device__ __forceinline__ float tree13(float* v, int lane) {
    {
        float o[13];
#pragma unroll
        for (int i = 0; i < 13; i++) o[i] = __shfl_xor_sync(0xffffffffu, v[i], 16);
        if (lane & 16) {
#pragma unroll
            for (int i = 0; i < 6; i++) v[i] = v[i + 7] + o[i + 7];
        } else {
#pragma unroll
            for (int i = 0; i < 7; i++) v[i] = v[i] + o[i];
        }
    }
    {
        float o[7];
#pragma unroll
        for (int i = 0; i < 7; i++) o[i] = __shfl_xor_sync(0xffffffffu, v[i], 8);
        if (!(lane & 16)) {
            if (lane & 8) { v[0] = v[4] + o[4]; v[1] = v[5] + o[5]; v[2] = v[6] + o[6]; }
            else { v[0] = v[0] + o[0]; v[1] = v[1] + o[1]; v[2] = v[2] + o[2]; v[3] = v[3] + o[3]; }
        } else {
            if (lane & 8) { v[0] = v[3] + o[3]; v[1] = v[4] + o[4]; v[2] = v[5] + o[5]; }
            else { v[0] = v[0] + o[0]; v[1] = v[1] + o[1]; v[2] = v[2] + o[2]; }
        }
    }
    {
        float o[4];
#pragma unroll
        for (int i = 0; i < 4; i++) o[i] = __shfl_xor_sync(0xffffffffu, v[i], 4);
        bool four = ((lane & 24) == 0);
        if (lane & 4) {
            v[0] = v[2] + o[2];
            if (four) v[1] = v[3] + o[3];
        } else {
            v[0] = v[0] + o[0];
            v[1] = v[1] + o[1];
        }
    }
    {
        float o0 = __shfl_xor_sync(0xffffffffu, v[0], 2);
        float o1 = __shfl_xor_sync(0xffffffffu, v[1], 2);
        v[0] = (lane & 2) ? (v[1] + o1) : (v[0] + o0);
    }
    {
        float o0 = __shfl_xor_sync(0xffffffffu, v[0], 1);
        v[0] = v[0] + o0;
    }
    return v[0];
}

__device__ __forceinline__ void do_batch2(
    const float* __restrict__ sm, const int* ids, int vmask,
    int ty0, int ty1, int ty2,
    const float* __restrict__ nodes, const int* __restrict__ edges,
    float* __restrict__ out,
    int lane, int sid, bool alive)
{
    int nd[2][3];
#pragma unroll
    for (int b = 0; b < 2; b++)
#pragma unroll
        for (int s = 0; s < 3; s++)
            nd[b][s] = __ldg(edges + ids[b] * 3 + s);

    const int gs = lane / 13;
    const int gl = lane - gs * 13;
    float gv0[2], gv1[2];
#pragma unroll
    for (int b = 0; b < 2; b++) {
        const float* p0 = nodes + nd[b][0] * DD;
        const float* p1 = nodes + nd[b][1] * DD;
        const float* p2 = nodes + nd[b][2] * DD;
        const float* ps = (gs == 0) ? p0 : ((gs == 1) ? p1 : p2);
        gv0[b] = __ldg(ps + gl);
        gv1[b] = (lane < 7) ? __ldg(p2 + 6 + lane) : 0.f;
    }

    const int ty[3] = {ty0, ty1, ty2};

    // ---- stage 1
    float4 t[3][2];
#pragma unroll
    for (int s = 0; s < 3; s++) {
        const float* wb = sm + S_BP + ty[s] * DD * RR;
        float4 bias = reinterpret_cast<const float4*>(sm + S_BPB + ty[s] * RR)[lane];
        t[s][0] = bias;
        t[s][1] = bias;
#pragma unroll
        for (int d = 0; d < DD; d++) {
            float4 w = reinterpret_cast<const float4*>(wb + d * RR)[lane];
            const int src = s * 13 + d;
#pragma unroll
            for (int b = 0; b < 2; b++) {
                float rnv = (src < 32) ? __shfl_sync(0xffffffffu, gv0[b], src)
                                       : __shfl_sync(0xffffffffu, gv1[b], src - 32);
                t[s][b].x = fmaf(rnv, w.x, t[s][b].x);
                t[s][b].y = fmaf(rnv, w.y, t[s][b].y);
                t[s][b].z = fmaf(rnv, w.z, t[s][b].z);
                t[s][b].w = fmaf(rnv, w.w, t[s][b].w);
            }
        }
#pragma unroll
        for (int b = 0; b < 2; b++) {
            t[s][b].x = fmaxf(t[s][b].x, 0.f);
            t[s][b].y = fmaxf(t[s][b].y, 0.f);
            t[s][b].z = fmaxf(t[s][b].z, 0.f);
            t[s][b].w = fmaxf(t[s][b].w, 0.f);
        }
    }

    // ---- stage 2 (edges handled sequentially to bound registers)
#pragma unroll
    for (int s = 0; s < 3; s++) {
        const int j = (s == 0) ? 1 : 0;
        const int k = (s == 2) ? 1 : 2;
        const float* wh = sm + S_HO + (s * NP + ty[s]) * DD * HOSTRIDE;
        const float* hb = sm + S_HOB + (s * NP + ty[s]) * DD;
#pragma unroll
        for (int b = 0; b < 2; b++) {
            float4 f;
            f.x = t[j][b].x * t[k][b].x;
            f.y = t[j][b].y * t[k][b].y;
            f.z = t[j][b].z * t[k][b].z;
            f.w = t[j][b].w * t[k][b].w;
            float ms[DD];
#pragma unroll
            for (int d = 0; d < DD; d++) {
                float4 w = reinterpret_cast<const float4*>(wh + d * HOSTRIDE)[lane];
                ms[d] = fmaf(f.w, w.w, fmaf(f.z, w.z, fmaf(f.y, w.y, f.x * w.x)));
            }
            float val = tree13(ms, lane);
            if (alive && ((vmask >> b) & 1)) {
                atomicAdd(out + nd[b][s] * DD + sid, val + hb[sid]);
            }
        }
    }
}

__global__ void __launch_bounds__(384, 2) k_main(
    const float* __restrict__ nodes,
    const float* __restrict__ bp_params,
    const float* __restrict__ bp_bias,
    const float* __restrict__ ho_params,   // [3][NP][128][13]
    const float* __restrict__ ho_bias,
    const int*   __restrict__ edges,
    const int*   __restrict__ et,
    float*       __restrict__ out)
{
    extern __shared__ float sm[];
    for (int i = threadIdx.x; i < NP * DD * RR; i += blockDim.x) sm[S_BP + i] = bp_params[i];
    for (int i = threadIdx.x; i < NP * RR; i += blockDim.x)      sm[S_BPB + i] = bp_bias[i];
#pragma unroll 4
    for (int i = threadIdx.x; i < 3 * NP * RR * DD; i += blockDim.x) {
        int d  = i % DD;
        int rd = i / DD;
        int r  = rd & (RR - 1);
        int sp = rd >> 7;
        sm[S_HO + (sp * DD + d) * HOSTRIDE + r] = ho_params[i];
    }
    for (int i = threadIdx.x; i < 3 * NP * DD; i += blockDim.x)  sm[S_HOB + i] = ho_bias[i];
    __syncthreads();

    const int lane = threadIdx.x & 31;
    const int wid  = blockIdx.x * (blockDim.x >> 5) + (threadIdx.x >> 5);
    const int nw   = gridDim.x * (blockDim.x >> 5);

    int pre[PBLK + 1];
    pre[0] = 0;
#pragma unroll
    for (int b = 0; b < PBLK; b++) pre[b + 1] = pre[b] + __ldg(&g_cnt[b]);
    const int total = pre[PBLK];

    const int b4 = (lane >> 4) & 1, b3 = (lane >> 3) & 1, b2 = (lane >> 2) & 1,
              b1 = (lane >> 1) & 1, b0 = lane & 1;
    const bool alive = (b0 == 0) && !(b1 && b2 && (b4 | b3));
    const int sid = 7 * b4 + (b4 ? 3 * b3 : 4 * b3) + 2 * b2 + b1;

#pragma unroll 1
    for (int u = wid; u < total; u += nw) {
        int bi = 0;
#pragma unroll
        for (int b = 1; b < PBLK; b++) bi += (u >= pre[b]);
        const int local = u - pre[bi];
        const int* gp = g_pairs + bi * PCAP * 2 + local * 2;
        int ids[2];
        ids[0] = gp[0];
        ids[1] = gp[1];
        int vmask = 1;
        if (ids[1] >= 0) vmask |= 2; else ids[1] = ids[0];
        int t0 = __ldg(et + ids[0] * 3 + 0);
        int t1 = __ldg(et + ids[0] * 3 + 1);
        int t2 = __ldg(et + ids[0] * 3 + 2);
        do_batch2(sm, ids, vmask, t0, t1, t2, nodes, edges, out, lane, sid, alive);
    }
}

extern "C" void kernel_launch(void* const* d_in, const int* in_sizes, int n_in,
                              void* d_out, int out_size) {
    const float* nodes      = (const float*)d_in[0];
    const float* bp_params  = (const float*)d_in[1];
    const float* bp_bias    = (const float*)d_in[2];
    const float* ho_params  = (const float*)d_in[3];
    const float* ho_bias    = (const float*)d_in[4];
    const int*   edges      = (const int*)d_in[5];
    const int*   edge_types = (const int*)d_in[6];
    float* out = (float*)d_out;

    int sms = 0;
    cudaDeviceGetAttribute(&sms, cudaDevAttrMultiProcessorCount, 0);
    if (sms <= 0) sms = 148;
    cudaFuncSetAttribute(k_main, cudaFuncAttributeMaxDynamicSharedMemorySize, S_TOT * 4);

    k_prep<<<PBLK, 1024>>>(edge_types, out);
    k_main<<<2 * sms, 384, S_TOT * 4>>>(nodes, bp_params, bp_bias, ho_params, ho_bias,
                                        edges, edge_types, out);
}

// round 7
// speedup vs baseline: 1.2874x; 1.2874x over previous
#include <cuda_runtime.h>

#define NN 4096
#define EE 16384
#define DD 13
#define RR 128
#define NP 4
#define HOSTRIDE 132
#define PBLK 8
#define EPB  (EE / PBLK)      // 2048 edges per prep block
#define GCAP 2304             // max ids per region: 512 full groups + padding

__device__ int g_groups[PBLK * GCAP];
__device__ int g_cnt4[PBLK];

// k_main smem layout (floats)
#define S_BP   0
#define S_BPB  (NP * DD * RR)
#define S_HO   (S_BPB + NP * RR)
#define S_HOB  (S_HO + 3 * NP * DD * HOSTRIDE)
#define S_TOT  (S_HOB + 3 * NP * DD)   // ~109.1 KiB

// ---- prep: per-region bucket sort by type key, emit padded groups of 4 ------
__global__ void __launch_bounds__(1024, 1) k_prep(const int* __restrict__ et,
                                                  float* __restrict__ out) {
    __shared__ int hist[64], bstart[64], cursor[64], gb[64];
    __shared__ short sorted[EPB];
    __shared__ unsigned char keys[EPB], skey[EPB];
    const int tid = threadIdx.x;
    const int bi  = blockIdx.x;
    const int base = bi * EPB;

    for (int i = tid; i < NN * DD / PBLK; i += 1024) out[bi * (NN * DD / PBLK) + i] = 0.f;
    for (int i = tid; i < GCAP; i += 1024) g_groups[bi * GCAP + i] = -1;

    if (tid < 64) hist[tid] = 0;
    __syncthreads();
    for (int i = tid; i < EPB; i += 1024) {
        int e = base + i;
        int k = __ldg(et + e * 3) * 16 + __ldg(et + e * 3 + 1) * 4 + __ldg(et + e * 3 + 2);
        keys[i] = (unsigned char)k;
        atomicAdd(&hist[k], 1);
    }
    __syncthreads();
    if (tid == 0) {
        int run = 0, rg = 0;
        for (int k = 0; k < 64; k++) {
            bstart[k] = run; cursor[k] = run; run += hist[k];
            gb[k] = rg; rg += (hist[k] + 3) >> 2;
        }
        g_cnt4[bi] = rg;
    }
    __syncthreads();
    for (int i = tid; i < EPB; i += 1024) {
        int k = keys[i];
        int pos = atomicAdd(&cursor[k], 1);
        sorted[pos] = (short)i;
        skey[pos] = (unsigned char)k;
    }
    __syncthreads();
    for (int i = tid; i < EPB; i += 1024) {
        int k = skey[i];
        int r = i - bstart[k];
        g_groups[bi * GCAP + gb[k] * 4 + r] = base + (int)sorted[i];
    }
}

// ---- warp reduction of 13 streams via redistribution tree -------------------
__device__ __forceinline__ float tree13(float* v, int lane) {
    {
        float o[13];
#pragma unroll
        for (int i = 0; i < 13; i++) o[i] = __shfl_xor_sync(0xffffffffu, v[i], 16);
        if (lane & 16) {
#pragma unroll
            for (int i = 0; i < 6; i++) v[i] = v[i + 7] + o[i + 7];
        } else {
#pragma unroll
            for (int i = 0; i < 7; i++) v[i] = v[i] + o[i];
        }
    }
    {
        float o[7];
#pragma unroll
        for (int i = 0; i < 7; i++) o[i] = __shfl_xor_sync(0xffffffffu, v[i], 8);
        if (!(lane & 16)) {
            if (lane & 8) { v[0] = v[4] + o[4]; v[1] = v[5] + o[5]; v[2] = v[6] + o[6]; }
            else { v[0] = v[0] + o[0]; v[1] = v[1] + o[1]; v[2] = v[2] + o[2]; v[3] = v[3] + o[3]; }
        } else {
            if (lane & 8) { v[0] = v[3] + o[3]; v[1] = v[4] + o[4]; v[2] = v[5] + o[5]; }
            else { v[0] = v[0] + o[0]; v[1] = v[1] + o[1]; v[2] = v[2] + o[2]; }
        }
    }
    {
        float o[4];
#pragma unroll
        for (int i = 0; i < 4; i++) o[i] = __shfl_xor_sync(0xffffffffu, v[i], 4);
        bool four = ((lane & 24) == 0);
        if (lane & 4) {
            v[0] = v[2] + o[2];
            if (four) v[1] = v[3] + o[3];
        } else {
            v[0] = v[0] + o[0];
            v[1] = v[1] + o[1];
        }
    }
    {
        float o0 = __shfl_xor_sync(0xffffffffu, v[0], 2);
        float o1 = __shfl_xor_sync(0xffffffffu, v[1], 2);
        v[0] = (lane & 2) ? (v[1] + o1) : (v[0] + o0);
    }
    {
        float o0 = __shfl_xor_sync(0xffffffffu, v[0], 1);
        v[0] = v[0] + o0;
    }
    return v[0];
}

__device__ __forceinline__ void do_batch4(
    const float* __restrict__ sm, const int* ids, int vmask,
    int ty0, int ty1, int ty2,
    const float* __restrict__ nodes, const int* __restrict__ edges,
    float* __restrict__ out,
    int lane, int sid, bool alive)
{
    int nd[4][3];
#pragma unroll
    for (int b = 0; b < 4; b++)
#pragma unroll
        for (int s = 0; s < 3; s++)
            nd[b][s] = __ldg(edges + ids[b] * 3 + s);

    const int gs = lane / 13;
    const int gl = lane - gs * 13;
    float gv0[4], gv1[4];
#pragma unroll
    for (int b = 0; b < 4; b++) {
        const float* p0 = nodes + nd[b][0] * DD;
        const float* p1 = nodes + nd[b][1] * DD;
        const float* p2 = nodes + nd[b][2] * DD;
        const float* ps = (gs == 0) ? p0 : ((gs == 1) ? p1 : p2);
        gv0[b] = __ldg(ps + gl);
        gv1[b] = (lane < 7) ? __ldg(p2 + 6 + lane) : 0.f;
    }

    const int ty[3] = {ty0, ty1, ty2};

    float4 t[3][4];
#pragma unroll
    for (int s = 0; s < 3; s++) {
        const float* wb = sm + S_BP + ty[s] * DD * RR;
        float4 bias = reinterpret_cast<const float4*>(sm + S_BPB + ty[s] * RR)[lane];
#pragma unroll
        for (int b = 0; b < 4; b++) t[s][b] = bias;
#pragma unroll
        for (int d = 0; d < DD; d++) {
            float4 w = reinterpret_cast<const float4*>(wb + d * RR)[lane];
            const int src = s * 13 + d;
#pragma unroll
            for (int b = 0; b < 4; b++) {
                float rnv = (src < 32) ? __shfl_sync(0xffffffffu, gv0[b], src)
                                       : __shfl_sync(0xffffffffu, gv1[b], src - 32);
                t[s][b].x = fmaf(rnv, w.x, t[s][b].x);
                t[s][b].y = fmaf(rnv, w.y, t[s][b].y);
                t[s][b].z = fmaf(rnv, w.z, t[s][b].z);
                t[s][b].w = fmaf(rnv, w.w, t[s][b].w);
            }
        }
#pragma unroll
        for (int b = 0; b < 4; b++) {
            t[s][b].x = fmaxf(t[s][b].x, 0.f);
            t[s][b].y = fmaxf(t[s][b].y, 0.f);
            t[s][b].z = fmaxf(t[s][b].z, 0.f);
            t[s][b].w = fmaxf(t[s][b].w, 0.f);
        }
    }

#pragma unroll
    for (int s = 0; s < 3; s++) {
        const int j = (s == 0) ? 1 : 0;
        const int k = (s == 2) ? 1 : 2;
        const float* wh = sm + S_HO + (s * NP + ty[s]) * DD * HOSTRIDE;
        const float* hb = sm + S_HOB + (s * NP + ty[s]) * DD;
#pragma unroll
        for (int p = 0; p < 4; p += 2) {
            float4 f[2];
#pragma unroll
            for (int q = 0; q < 2; q++) {
                f[q].x = t[j][p + q].x * t[k][p + q].x;
                f[q].y = t[j][p + q].y * t[k][p + q].y;
                f[q].z = t[j][p + q].z * t[k][p + q].z;
                f[q].w = t[j][p + q].w * t[k][p + q].w;
            }
            float ms[2][DD];
#pragma unroll
            for (int d = 0; d < DD; d++) {
                float4 w = reinterpret_cast<const float4*>(wh + d * HOSTRIDE)[lane];
#pragma unroll
                for (int q = 0; q < 2; q++) {
                    ms[q][d] = fmaf(f[q].w, w.w,
                               fmaf(f[q].z, w.z,
                               fmaf(f[q].y, w.y, f[q].x * w.x)));
                }
            }
#pragma unroll
            for (int q = 0; q < 2; q++) {
                float val = tree13(ms[q], lane);
                if (alive && ((vmask >> (p + q)) & 1)) {
                    atomicAdd(out + nd[p + q][s] * DD + sid, val + hb[sid]);
                }
            }
        }
    }
}

__global__ void __launch_bounds__(512, 1) k_main(
    const float* __restrict__ nodes,
    const float* __restrict__ bp_params,
    const float* __restrict__ bp_bias,
    const float* __restrict__ ho_params,   // [3][NP][128][13]
    const float* __restrict__ ho_bias,
    const int*   __restrict__ edges,
    const int*   __restrict__ et,
    float*       __restrict__ out)
{
    extern __shared__ float sm[];
    for (int i = threadIdx.x; i < NP * DD * RR; i += blockDim.x) sm[S_BP + i] = bp_params[i];
    for (int i = threadIdx.x; i < NP * RR; i += blockDim.x)      sm[S_BPB + i] = bp_bias[i];
#pragma unroll 4
    for (int i = threadIdx.x; i < 3 * NP * RR * DD; i += blockDim.x) {
        int d  = i % DD;
        int rd = i / DD;
        int r  = rd & (RR - 1);
        int sp = rd >> 7;
        sm[S_HO + (sp * DD + d) * HOSTRIDE + r] = ho_params[i];
    }
    for (int i = threadIdx.x; i < 3 * NP * DD; i += blockDim.x)  sm[S_HOB + i] = ho_bias[i];
    __syncthreads();

    const int lane = threadIdx.x & 31;
    const int wid  = blockIdx.x * (blockDim.x >> 5) + (threadIdx.x >> 5);
    const int nw   = gridDim.x * (blockDim.x >> 5);

    int pre[PBLK + 1];
    pre[0] = 0;
#pragma unroll
    for (int b = 0; b < PBLK; b++) pre[b + 1] = pre[b] + __ldg(&g_cnt4[b]);
    const int total = pre[PBLK];

    const int b4 = (lane >> 4) & 1, b3 = (lane >> 3) & 1, b2 = (lane >> 2) & 1,
              b1 = (lane >> 1) & 1, b0 = lane & 1;
    const bool alive = (b0 == 0) && !(b1 && b2 && (b4 | b3));
    const int sid = 7 * b4 + (b4 ? 3 * b3 : 4 * b3) + 2 * b2 + b1;

#pragma unroll 1
    for (int u = wid; u < total; u += nw) {
        int bi = 0;
#pragma unroll
        for (int b = 1; b < PBLK; b++) bi += (u >= pre[b]);
        const int local = u - pre[bi];
        const int* gp = g_groups + bi * GCAP + local * 4;
        int ids[4];
#pragma unroll
        for (int b = 0; b < 4; b++) ids[b] = gp[b];
        int vmask = 1;
#pragma unroll
        for (int b = 1; b < 4; b++) {
            if (ids[b] >= 0) vmask |= (1 << b);
            else ids[b] = ids[0];
        }
        int t0 = __ldg(et + ids[0] * 3 + 0);
        int t1 = __ldg(et + ids[0] * 3 + 1);
        int t2 = __ldg(et + ids[0] * 3 + 2);
        do_batch4(sm, ids, vmask, t0, t1, t2, nodes, edges, out, lane, sid, alive);
    }
}

extern "C" void kernel_launch(void* const* d_in, const int* in_sizes, int n_in,
                              void* d_out, int out_size) {
    const float* nodes      = (const float*)d_in[0];
    const float* bp_params  = (const float*)d_in[1];
    const float* bp_bias    = (const float*)d_in[2];
    const float* ho_params  = (const float*)d_in[3];
    const float* ho_bias    = (const float*)d_in[4];
    const int*   edges      = (const int*)d_in[5];
    const int*   edge_types = (const int*)d_in[6];
    float* out = (float*)d_out;

    int sms = 0;
    cudaDeviceGetAttribute(&sms, cudaDevAttrMultiProcessorCount, 0);
    if (sms <= 0) sms = 148;
    cudaFuncSetAttribute(k_main, cudaFuncAttributeMaxDynamicSharedMemorySize, S_TOT * 4);

    k_prep<<<PBLK, 1024>>>(edge_types, out);
    k_main<<<sms, 512, S_TOT * 4>>>(nodes, bp_params, bp_bias, ho_params, ho_bias,
                                    edges, edge_types, out);
}